// round 9
// baseline (speedup 1.0000x reference)
#include <cuda_runtime.h>

#define NB  4
#define NSQ 512
#define NSK 512
#define ND  512
#define NS  128

typedef unsigned long long ull;

// ---- packed f32x2 helpers ----
__device__ __forceinline__ void fma2(ull& d, ull a, ull b) {
    asm("fma.rn.f32x2 %0, %1, %2, %0;" : "+l"(d) : "l"(a), "l"(b));
}
__device__ __forceinline__ ull add2(ull a, ull b) {
    ull r; asm("add.rn.f32x2 %0, %1, %2;" : "=l"(r) : "l"(a), "l"(b)); return r;
}
__device__ __forceinline__ ull pack2(float x, float y) {
    ull r; asm("mov.b64 %0, {%1, %2};" : "=l"(r) : "f"(x), "f"(y)); return r;
}
__device__ __forceinline__ float2 unpack2(ull v) {
    float2 r; asm("mov.b64 {%0, %1}, %2;" : "=f"(r.x), "=f"(r.y) : "l"(v)); return r;
}

#define SMASK 0x7fffffff7fffffffULL

// ---- scratch (allocation-free) ----
__device__ __align__(16) float g_Wqh[ND * NS];
__device__ __align__(16) float g_Wkh[ND * NS];
__device__ __align__(16) float g_cA[NS];
__device__ __align__(16) float g_cK[NS];
__device__ __align__(16) float g_sg[NS];            // +-0.5 by sign of w2
__device__ __align__(16) float g_A2[NB * NSQ * NS]; // (q@Wqh + cA) * w2
__device__ __align__(16) float g_K2[NB * NSK * NS]; // (k@Wkh + cK) * w2
__device__ __align__(16) float g_CA[NB * NSQ];      // 0.5 * rowsum(A2)
__device__ __align__(16) float g_CK[NB * NSK];      // 0.5 * rowsum(K2)

// ---------------------------------------------------------------------------
// fold: Wqh = Wq @ W1[:S], Wkh = Wk @ W1[S:]  (+ bias/sg in block x==64)
// ---------------------------------------------------------------------------
__global__ void fold_kernel(const float* __restrict__ Wq,
                            const float* __restrict__ Wk,
                            const float* __restrict__ W1,
                            const float* __restrict__ bq,
                            const float* __restrict__ bk,
                            const float* __restrict__ b1,
                            const float* __restrict__ W2) {
    int v = blockIdx.y, s = threadIdx.x;
    if (blockIdx.x == 64) {
        if (v == 0) {
            float a = b1[s];
#pragma unroll 8
            for (int t = 0; t < NS; t++) a = fmaf(bq[t], W1[t * NS + s], a);
            g_cA[s] = a;
            g_sg[s] = (W2[s] >= 0.f) ? 0.5f : -0.5f;
        } else {
            float c = 0.f;
#pragma unroll 8
            for (int t = 0; t < NS; t++) c = fmaf(bk[t], W1[(NS + t) * NS + s], c);
            g_cK[s] = c;
        }
        return;
    }
    int d0 = blockIdx.x * 8;
    __shared__ float wr[8][NS];
    const float* Wsrc = v ? Wk : Wq;
#pragma unroll
    for (int j = 0; j < 8; j++) wr[j][s] = Wsrc[(d0 + j) * NS + s];
    __syncthreads();
    const float* W1p = W1 + (v ? NS * NS : 0);
    float acc[8] = {};
#pragma unroll 8
    for (int t = 0; t < NS; t++) {
        float w = W1p[t * NS + s];
#pragma unroll
        for (int j = 0; j < 8; j++) acc[j] = fmaf(wr[j][t], w, acc[j]);
    }
    float* O = v ? g_Wkh : g_Wqh;
#pragma unroll
    for (int j = 0; j < 8; j++) O[(d0 + j) * NS + s] = acc[j];
}

// ---------------------------------------------------------------------------
// proj: A2 = (X @ Wfold + cb) * w2, plus CA = 0.5*rowsum(A2)  (unchanged)
// ---------------------------------------------------------------------------
#define ASP 36
#define BSP 132

__global__ __launch_bounds__(256) void proj_kernel(const float* __restrict__ Xq,
                                                   const float* __restrict__ Xk,
                                                   const float* __restrict__ W2) {
    int v = blockIdx.y;
    const float* X    = v ? Xk : Xq;
    const float* Wf   = v ? g_Wkh : g_Wqh;
    const float* bias = v ? g_cK : g_cA;
    float* O          = v ? g_K2 : g_A2;
    float* CS         = v ? g_CK : g_CA;

    int m0  = blockIdx.x * 32;
    int tid = threadIdx.x;
    int w   = tid >> 5, lane = tid & 31;
    int qc  = lane >> 2, dc = lane & 3;

    __shared__ float As[16][ASP];
    __shared__ float Bs[16][BSP];
    __shared__ float red[8][32];

    int r  = tid >> 3, c2 = (tid & 7) * 2;
    int rb = tid >> 4, cw = (tid & 15) * 8;

    float2 xv = *(const float2*)&X[(m0 + r) * ND + c2];
    float4 w0 = *(const float4*)&Wf[rb * NS + cw];
    float4 w1 = *(const float4*)&Wf[rb * NS + cw + 4];

    ull acc[4][2] = {};
    int db = w * 16 + dc * 4;

    for (int t = 0; t < ND / 16; t++) {
        As[c2][r] = xv.x; As[c2 + 1][r] = xv.y;
        *(float4*)&Bs[rb][cw]     = w0;
        *(float4*)&Bs[rb][cw + 4] = w1;
        __syncthreads();
        if (t + 1 < ND / 16) {
            int k0 = (t + 1) * 16;
            xv = *(const float2*)&X[(m0 + r) * ND + k0 + c2];
            w0 = *(const float4*)&Wf[(k0 + rb) * NS + cw];
            w1 = *(const float4*)&Wf[(k0 + rb) * NS + cw + 4];
        }
#pragma unroll
        for (int kk = 0; kk < 16; kk++) {
            float4 a = *(float4*)&As[kk][qc * 4];
            ulonglong2 bv = *(ulonglong2*)&Bs[kk][db];
            ull p0 = pack2(a.x, a.x), p1 = pack2(a.y, a.y);
            ull p2 = pack2(a.z, a.z), p3 = pack2(a.w, a.w);
            fma2(acc[0][0], p0, bv.x); fma2(acc[0][1], p0, bv.y);
            fma2(acc[1][0], p1, bv.x); fma2(acc[1][1], p1, bv.y);
            fma2(acc[2][0], p2, bv.x); fma2(acc[2][1], p2, bv.y);
            fma2(acc[3][0], p3, bv.x); fma2(acc[3][1], p3, bv.y);
        }
        __syncthreads();
    }

    float4 cbv = *(const float4*)&bias[db];
    float4 w2v = *(const float4*)&W2[db];
    float rsum[4];
#pragma unroll
    for (int j = 0; j < 4; j++) {
        int row = m0 + qc * 4 + j;
        float2 p0 = unpack2(acc[j][0]), p1 = unpack2(acc[j][1]);
        float4 o;
        o.x = (p0.x + cbv.x) * w2v.x; o.y = (p0.y + cbv.y) * w2v.y;
        o.z = (p1.x + cbv.z) * w2v.z; o.w = (p1.y + cbv.w) * w2v.w;
        *(float4*)&O[row * NS + db] = o;
        rsum[j] = o.x + o.y + o.z + o.w;
    }
#pragma unroll
    for (int j = 0; j < 4; j++) {
        rsum[j] += __shfl_xor_sync(0xffffffffu, rsum[j], 1);
        rsum[j] += __shfl_xor_sync(0xffffffffu, rsum[j], 2);
    }
    if (dc == 0) {
#pragma unroll
        for (int j = 0; j < 4; j++) red[w][qc * 4 + j] = rsum[j];
    }
    __syncthreads();
    if (tid < 32) {
        float s = 0.f;
#pragma unroll
        for (int ww = 0; ww < 8; ww++) s += red[ww][tid];
        CS[m0 + tid] = 0.5f * s;
    }
}

// ---------------------------------------------------------------------------
// scores + softmax + attn write.  128 thr, KT=64 -> 57KB smem -> 3-4 CTA/SM.
// thread = 1 kk x 4 q (two q-groups). f32x2 add (fma) + AND-abs (alu) + fma2.
// ---------------------------------------------------------------------------
#define TQ  8
#define KT  64
#define KMP 132
#define SCP 516

__global__ __launch_bounds__(128) void score_kernel(const int* __restrict__ mask,
                                                    const float* __restrict__ b2,
                                                    float* __restrict__ attn_out) {
    extern __shared__ float sm[];
    float* qcs = sm;                    // TQ*NS  = 1024 f
    float* sgs = qcs + TQ * NS;         // 128 f
    float* cks = sgs + NS;              // 512 f
    float* cas = cks + NSK;             // 16 f
    float* kms = cas + 16;              // KT*KMP = 8448 f
    float* scT = kms + KT * KMP;        // TQ*516 = 4128 f

    int bx = blockIdx.x;
    int b  = bx >> 6;
    int q0 = (bx & 63) * TQ;
    int tid = threadIdx.x;
    int kk = tid & 63;
    int qh = (tid >> 6) * 4;            // 0 or 4

    {
        const float4* A4 = (const float4*)&g_A2[(b * NSQ + q0) * NS];
        ((float4*)qcs)[tid]       = A4[tid];
        ((float4*)qcs)[tid + 128] = A4[tid + 128];
        if (tid < 32) ((float4*)sgs)[tid] = ((const float4*)g_sg)[tid];
        ((float4*)cks)[tid] = ((const float4*)(g_CK + b * NSK))[tid];
        if (tid < TQ) cas[tid] = g_CA[b * NSQ + q0 + tid] + b2[0];
    }

    const float* qp = qcs + qh * NS;

    for (int k0 = 0; k0 < NSK; k0 += KT) {
        __syncthreads();
        const float4* K4 = (const float4*)&g_K2[(b * NSK + k0) * NS];
#pragma unroll
        for (int i = 0; i < 16; i++) {
            int idx = i * 128 + tid;
            int kr = idx >> 5, s4 = idx & 31;
            *(float4*)&kms[kr * KMP + s4 * 4] = K4[idx];
        }
        __syncthreads();

        ull acc[4] = {};
#pragma unroll 8
        for (int s = 0; s < NS; s += 4) {
            ulonglong2 kv = *(ulonglong2*)&kms[kk * KMP + s];
            ulonglong2 sg = *(ulonglong2*)&sgs[s];
#pragma unroll
            for (int q = 0; q < 4; q++) {
                ulonglong2 qv = *(ulonglong2*)&qp[q * NS + s];
                ull x0 = add2(qv.x, kv.x) & SMASK;
                ull x1 = add2(qv.y, kv.y) & SMASK;
                fma2(acc[q], sg.x, x0);
                fma2(acc[q], sg.y, x1);
            }
        }

        int kg = k0 + kk;
        float ckv = cks[kg];
        const int* mrow = mask + (b * NSQ + q0 + qh) * NSK + kg;
#pragma unroll
        for (int q = 0; q < 4; q++) {
            float2 p = unpack2(acc[q]);
            float s = p.x + p.y + cas[qh + q] + ckv;
            if (mrow[q * NSK] == 0) s = -1e9f;
            scT[(qh + q) * SCP + kg] = s;
        }
    }
    __syncthreads();

    // softmax: warp w handles q = 2w, 2w+1; write normalized attn to gmem
    {
        int w = tid >> 5, lane = tid & 31;
#pragma unroll
        for (int qq = 0; qq < 2; qq++) {
            int q = w * 2 + qq;
            float4 v[4];
            float mx = -3.0e38f;
#pragma unroll
            for (int j = 0; j < 4; j++) {
                v[j] = *(float4*)&scT[q * SCP + j * 128 + lane * 4];
                mx = fmaxf(mx, fmaxf(fmaxf(v[j].x, v[j].y), fmaxf(v[j].z, v[j].w)));
            }
#pragma unroll
            for (int o = 16; o; o >>= 1) mx = fmaxf(mx, __shfl_xor_sync(0xffffffffu, mx, o));
            float sum = 0.f;
#pragma unroll
            for (int j = 0; j < 4; j++) {
                v[j].x = __expf(v[j].x - mx); v[j].y = __expf(v[j].y - mx);
                v[j].z = __expf(v[j].z - mx); v[j].w = __expf(v[j].w - mx);
                sum += v[j].x + v[j].y + v[j].z + v[j].w;
            }
#pragma unroll
            for (int o = 16; o; o >>= 1) sum += __shfl_xor_sync(0xffffffffu, sum, o);
            float inv = 1.0f / sum;
            float* arow = attn_out + (b * NSQ + q0 + q) * NSK;
#pragma unroll
            for (int j = 0; j < 4; j++) {
                float4 wv;
                wv.x = v[j].x * inv; wv.y = v[j].y * inv;
                wv.z = v[j].z * inv; wv.w = v[j].w * inv;
                *(float4*)&arow[j * 128 + lane * 4] = wv;
            }
        }
    }
}

// ---------------------------------------------------------------------------
// AV GEMM: BM=64 x BN=128 x BK=16, 512 thr (16 warps/SM), double-buffered.
// V stored DUPLICATED in smem -> LDS.128 yields pre-packed (v,v) f32x2 operands.
// attn read as ulonglong2 -> pre-packed q-pairs. Zero movs in the hot loop.
// Warp: qb=(w>>3)*32 q-range, db=(w&7)*16 d-range; thread 4q x 4d. grid (4,8,4).
// ---------------------------------------------------------------------------
__global__ __launch_bounds__(512) void av_kernel(const float* __restrict__ attn,
                                                 const float* __restrict__ Vv,
                                                 float* __restrict__ out) {
    int b  = blockIdx.z;
    int q0 = blockIdx.y * 64;
    int d0 = blockIdx.x * 128;
    int tid = threadIdx.x;
    int w = tid >> 5, lane = tid & 31;
    int qc = lane >> 2, dc = lane & 3;
    int qb = (w >> 3) * 32, db = (w & 7) * 16;

    __shared__ float At[2][16][68];     // attn^T [k][q]
    __shared__ float Bsd[2][16][256];   // V duplicated [k][2d],[2d+1]

    const float* Ab = attn + (b * NSQ + q0) * NSK;
    const float* Vb = Vv + b * NSK * ND + d0;

    int ra = tid >> 2, ca = (tid & 3) * 4;     // tid<256: attn q=ra, k=ca..ca+3
    int rb = tid >> 5, cb = (tid & 31) * 4;    // V: k=rb (0..15), d=cb..cb+3

    float4 a = make_float4(0.f, 0.f, 0.f, 0.f);
    if (tid < 256) a = *(const float4*)&Ab[ra * NSK + ca];
    float4 v = *(const float4*)&Vb[rb * ND + cb];
    if (tid < 256) {
        At[0][ca][ra] = a.x; At[0][ca + 1][ra] = a.y;
        At[0][ca + 2][ra] = a.z; At[0][ca + 3][ra] = a.w;
    }
    {
        float4 d01 = make_float4(v.x, v.x, v.y, v.y);
        float4 d23 = make_float4(v.z, v.z, v.w, v.w);
        *(float4*)&Bsd[0][rb][2 * cb]     = d01;
        *(float4*)&Bsd[0][rb][2 * cb + 4] = d23;
    }
    __syncthreads();

    ull acc[2][4] = {};

    for (int t = 0; t < NSK / 16; t++) {
        int cur = t & 1;
        if (t + 1 < NSK / 16) {
            int k0 = (t + 1) * 16;
            if (tid < 256) a = *(const float4*)&Ab[ra * NSK + k0 + ca];
            v = *(const float4*)&Vb[(k0 + rb) * ND + cb];
        }
#pragma unroll
        for (int kk = 0; kk < 16; kk++) {
            ulonglong2 qp = *(ulonglong2*)&At[cur][kk][qb + qc * 4];
            ulonglong2 w0 = *(ulonglong2*)&Bsd[cur][kk][2 * (db + dc * 4)];
            ulonglong2 w1 = *(ulonglong2*)&Bsd[cur][kk][2 * (db + dc * 4) + 4];
            fma2(acc[0][0], qp.x, w0.x); fma2(acc[0][1], qp.x, w0.y);
            fma2(acc[0][2], qp.x, w1.x); fma2(acc[0][3], qp.x, w1.y);
            fma2(acc[1][0], qp.y, w0.x); fma2(acc[1][1], qp.y, w0.y);
            fma2(acc[1][2], qp.y, w1.x); fma2(acc[1][3], qp.y, w1.y);
        }
        if (t + 1 < NSK / 16) {
            int nxt = cur ^ 1;
            if (tid < 256) {
                At[nxt][ca][ra] = a.x; At[nxt][ca + 1][ra] = a.y;
                At[nxt][ca + 2][ra] = a.z; At[nxt][ca + 3][ra] = a.w;
            }
            float4 d01 = make_float4(v.x, v.x, v.y, v.y);
            float4 d23 = make_float4(v.z, v.z, v.w, v.w);
            *(float4*)&Bsd[nxt][rb][2 * cb]     = d01;
            *(float4*)&Bsd[nxt][rb][2 * cb + 4] = d23;
        }
        __syncthreads();
    }

    // epilogue: acc[p][j] = (out[qa+2p][dj], out[qa+2p+1][dj])
    int qa = q0 + qb + qc * 4;
    int dg = d0 + db + dc * 4;
#pragma unroll
    for (int p = 0; p < 2; p++) {
        float2 t0 = unpack2(acc[p][0]), t1 = unpack2(acc[p][1]);
        float2 t2 = unpack2(acc[p][2]), t3 = unpack2(acc[p][3]);
        float4 r0 = make_float4(t0.x, t1.x, t2.x, t3.x);
        float4 r1 = make_float4(t0.y, t1.y, t2.y, t3.y);
        *(float4*)&out[(b * NSQ + qa + 2 * p) * ND + dg] = r0;
        *(float4*)&out[(b * NSQ + qa + 2 * p + 1) * ND + dg] = r1;
    }
}

// ---------------------------------------------------------------------------
#define SMEM_SC ((TQ * NS + NS + NSK + 16 + KT * KMP + TQ * SCP) * 4)

extern "C" void kernel_launch(void* const* d_in, const int* in_sizes, int n_in,
                              void* d_out, int out_size) {
    const float* query = (const float*)d_in[0];
    const float* key   = (const float*)d_in[1];
    const float* value = (const float*)d_in[2];
    const int*   mask  = (const int*)d_in[3];
    const float* Wq = (const float*)d_in[4];
    const float* bq = (const float*)d_in[5];
    const float* Wk = (const float*)d_in[6];
    const float* bk = (const float*)d_in[7];
    const float* W1 = (const float*)d_in[8];
    const float* b1 = (const float*)d_in[9];
    const float* W2 = (const float*)d_in[10];
    const float* b2 = (const float*)d_in[11];

    float* out  = (float*)d_out;
    float* attn = out + NB * NSQ * ND;

    cudaFuncSetAttribute(score_kernel,
                         cudaFuncAttributeMaxDynamicSharedMemorySize, SMEM_SC);

    fold_kernel<<<dim3(65, 2), 128>>>(Wq, Wk, W1, bq, bk, b1, W2);
    proj_kernel<<<dim3(64, 2), 256>>>(query, key, W2);
    score_kernel<<<NB * NSQ / TQ, 128, SMEM_SC>>>(mask, b2, attn);
    av_kernel<<<dim3(4, 8, 4), 512>>>(attn, value, out);
}

// round 10
// speedup vs baseline: 1.3448x; 1.3448x over previous
#include <cuda_runtime.h>

#define NB  4
#define NSQ 512
#define NSK 512
#define ND  512
#define NS  128

typedef unsigned long long ull;

// ---- packed f32x2 helpers ----
__device__ __forceinline__ void fma2(ull& d, ull a, ull b) {
    asm("fma.rn.f32x2 %0, %1, %2, %0;" : "+l"(d) : "l"(a), "l"(b));
}
__device__ __forceinline__ ull add2(ull a, ull b) {
    ull r; asm("add.rn.f32x2 %0, %1, %2;" : "=l"(r) : "l"(a), "l"(b)); return r;
}
__device__ __forceinline__ ull pack2(float x, float y) {
    ull r; asm("mov.b64 %0, {%1, %2};" : "=l"(r) : "f"(x), "f"(y)); return r;
}
__device__ __forceinline__ float2 unpack2(ull v) {
    float2 r; asm("mov.b64 {%0, %1}, %2;" : "=f"(r.x), "=f"(r.y) : "l"(v)); return r;
}

#define SMASK 0x7fffffff7fffffffULL

// ---- scratch (allocation-free) ----
__device__ __align__(16) float g_Wqh[ND * NS];
__device__ __align__(16) float g_Wkh[ND * NS];
__device__ __align__(16) float g_cA[NS];
__device__ __align__(16) float g_cK[NS];
__device__ __align__(16) float g_sg[NS];            // +-0.5 by sign of w2
__device__ __align__(16) float g_A2[NB * NSQ * NS]; // (q@Wqh + cA) * w2
__device__ __align__(16) float g_K2[NB * NSK * NS]; // (k@Wkh + cK) * w2
__device__ __align__(16) float g_CA[NB * NSQ];      // 0.5 * rowsum(A2)
__device__ __align__(16) float g_CK[NB * NSK];      // 0.5 * rowsum(K2)

// ---------------------------------------------------------------------------
// fold: Wqh = Wq @ W1[:S], Wkh = Wk @ W1[S:]  (+ bias/sg in block x==64)
// ---------------------------------------------------------------------------
__global__ void fold_kernel(const float* __restrict__ Wq,
                            const float* __restrict__ Wk,
                            const float* __restrict__ W1,
                            const float* __restrict__ bq,
                            const float* __restrict__ bk,
                            const float* __restrict__ b1,
                            const float* __restrict__ W2) {
    int v = blockIdx.y, s = threadIdx.x;
    if (blockIdx.x == 64) {
        if (v == 0) {
            float a = b1[s];
#pragma unroll 8
            for (int t = 0; t < NS; t++) a = fmaf(bq[t], W1[t * NS + s], a);
            g_cA[s] = a;
            g_sg[s] = (W2[s] >= 0.f) ? 0.5f : -0.5f;
        } else {
            float c = 0.f;
#pragma unroll 8
            for (int t = 0; t < NS; t++) c = fmaf(bk[t], W1[(NS + t) * NS + s], c);
            g_cK[s] = c;
        }
        return;
    }
    int d0 = blockIdx.x * 8;
    __shared__ float wr[8][NS];
    const float* Wsrc = v ? Wk : Wq;
#pragma unroll
    for (int j = 0; j < 8; j++) wr[j][s] = Wsrc[(d0 + j) * NS + s];
    __syncthreads();
    const float* W1p = W1 + (v ? NS * NS : 0);
    float acc[8] = {};
#pragma unroll 8
    for (int t = 0; t < NS; t++) {
        float w = W1p[t * NS + s];
#pragma unroll
        for (int j = 0; j < 8; j++) acc[j] = fmaf(wr[j][t], w, acc[j]);
    }
    float* O = v ? g_Wkh : g_Wqh;
#pragma unroll
    for (int j = 0; j < 8; j++) O[(d0 + j) * NS + s] = acc[j];
}

// ---------------------------------------------------------------------------
// proj: A2 = (X @ Wfold + cb) * w2, plus CA = 0.5*rowsum(A2)  (unchanged)
// ---------------------------------------------------------------------------
#define ASP 36
#define BSP 132

__global__ __launch_bounds__(256) void proj_kernel(const float* __restrict__ Xq,
                                                   const float* __restrict__ Xk,
                                                   const float* __restrict__ W2) {
    int v = blockIdx.y;
    const float* X    = v ? Xk : Xq;
    const float* Wf   = v ? g_Wkh : g_Wqh;
    const float* bias = v ? g_cK : g_cA;
    float* O          = v ? g_K2 : g_A2;
    float* CS         = v ? g_CK : g_CA;

    int m0  = blockIdx.x * 32;
    int tid = threadIdx.x;
    int w   = tid >> 5, lane = tid & 31;
    int qc  = lane >> 2, dc = lane & 3;

    __shared__ float As[16][ASP];
    __shared__ float Bs[16][BSP];
    __shared__ float red[8][32];

    int r  = tid >> 3, c2 = (tid & 7) * 2;
    int rb = tid >> 4, cw = (tid & 15) * 8;

    float2 xv = *(const float2*)&X[(m0 + r) * ND + c2];
    float4 w0 = *(const float4*)&Wf[rb * NS + cw];
    float4 w1 = *(const float4*)&Wf[rb * NS + cw + 4];

    ull acc[4][2] = {};
    int db = w * 16 + dc * 4;

    for (int t = 0; t < ND / 16; t++) {
        As[c2][r] = xv.x; As[c2 + 1][r] = xv.y;
        *(float4*)&Bs[rb][cw]     = w0;
        *(float4*)&Bs[rb][cw + 4] = w1;
        __syncthreads();
        if (t + 1 < ND / 16) {
            int k0 = (t + 1) * 16;
            xv = *(const float2*)&X[(m0 + r) * ND + k0 + c2];
            w0 = *(const float4*)&Wf[(k0 + rb) * NS + cw];
            w1 = *(const float4*)&Wf[(k0 + rb) * NS + cw + 4];
        }
#pragma unroll
        for (int kk = 0; kk < 16; kk++) {
            float4 a = *(float4*)&As[kk][qc * 4];
            ulonglong2 bv = *(ulonglong2*)&Bs[kk][db];
            ull p0 = pack2(a.x, a.x), p1 = pack2(a.y, a.y);
            ull p2 = pack2(a.z, a.z), p3 = pack2(a.w, a.w);
            fma2(acc[0][0], p0, bv.x); fma2(acc[0][1], p0, bv.y);
            fma2(acc[1][0], p1, bv.x); fma2(acc[1][1], p1, bv.y);
            fma2(acc[2][0], p2, bv.x); fma2(acc[2][1], p2, bv.y);
            fma2(acc[3][0], p3, bv.x); fma2(acc[3][1], p3, bv.y);
        }
        __syncthreads();
    }

    float4 cbv = *(const float4*)&bias[db];
    float4 w2v = *(const float4*)&W2[db];
    float rsum[4];
#pragma unroll
    for (int j = 0; j < 4; j++) {
        int row = m0 + qc * 4 + j;
        float2 p0 = unpack2(acc[j][0]), p1 = unpack2(acc[j][1]);
        float4 o;
        o.x = (p0.x + cbv.x) * w2v.x; o.y = (p0.y + cbv.y) * w2v.y;
        o.z = (p1.x + cbv.z) * w2v.z; o.w = (p1.y + cbv.w) * w2v.w;
        *(float4*)&O[row * NS + db] = o;
        rsum[j] = o.x + o.y + o.z + o.w;
    }
#pragma unroll
    for (int j = 0; j < 4; j++) {
        rsum[j] += __shfl_xor_sync(0xffffffffu, rsum[j], 1);
        rsum[j] += __shfl_xor_sync(0xffffffffu, rsum[j], 2);
    }
    if (dc == 0) {
#pragma unroll
        for (int j = 0; j < 4; j++) red[w][qc * 4 + j] = rsum[j];
    }
    __syncthreads();
    if (tid < 32) {
        float s = 0.f;
#pragma unroll
        for (int ww = 0; ww < 8; ww++) s += red[ww][tid];
        CS[m0 + tid] = 0.5f * s;
    }
}

// ---------------------------------------------------------------------------
// scores + softmax + attn write (R9 version, measured ~19.5us)
// 128 thr, KT=64 -> 57KB smem -> 3-4 CTA/SM. thread = 1 kk x 4 q.
// ---------------------------------------------------------------------------
#define TQ  8
#define KT  64
#define KMP 132
#define SCP 516

__global__ __launch_bounds__(128) void score_kernel(const int* __restrict__ mask,
                                                    const float* __restrict__ b2,
                                                    float* __restrict__ attn_out) {
    extern __shared__ float sm[];
    float* qcs = sm;                    // TQ*NS  = 1024 f
    float* sgs = qcs + TQ * NS;         // 128 f
    float* cks = sgs + NS;              // 512 f
    float* cas = cks + NSK;             // 16 f
    float* kms = cas + 16;              // KT*KMP = 8448 f
    float* scT = kms + KT * KMP;        // TQ*516 = 4128 f

    int bx = blockIdx.x;
    int b  = bx >> 6;
    int q0 = (bx & 63) * TQ;
    int tid = threadIdx.x;
    int kk = tid & 63;
    int qh = (tid >> 6) * 4;            // 0 or 4

    {
        const float4* A4 = (const float4*)&g_A2[(b * NSQ + q0) * NS];
        ((float4*)qcs)[tid]       = A4[tid];
        ((float4*)qcs)[tid + 128] = A4[tid + 128];
        if (tid < 32) ((float4*)sgs)[tid] = ((const float4*)g_sg)[tid];
        ((float4*)cks)[tid] = ((const float4*)(g_CK + b * NSK))[tid];
        if (tid < TQ) cas[tid] = g_CA[b * NSQ + q0 + tid] + b2[0];
    }

    const float* qp = qcs + qh * NS;

    for (int k0 = 0; k0 < NSK; k0 += KT) {
        __syncthreads();
        const float4* K4 = (const float4*)&g_K2[(b * NSK + k0) * NS];
#pragma unroll
        for (int i = 0; i < 16; i++) {
            int idx = i * 128 + tid;
            int kr = idx >> 5, s4 = idx & 31;
            *(float4*)&kms[kr * KMP + s4 * 4] = K4[idx];
        }
        __syncthreads();

        ull acc[4] = {};
#pragma unroll 8
        for (int s = 0; s < NS; s += 4) {
            ulonglong2 kv = *(ulonglong2*)&kms[kk * KMP + s];
            ulonglong2 sg = *(ulonglong2*)&sgs[s];
#pragma unroll
            for (int q = 0; q < 4; q++) {
                ulonglong2 qv = *(ulonglong2*)&qp[q * NS + s];
                ull x0 = add2(qv.x, kv.x) & SMASK;
                ull x1 = add2(qv.y, kv.y) & SMASK;
                fma2(acc[q], sg.x, x0);
                fma2(acc[q], sg.y, x1);
            }
        }

        int kg = k0 + kk;
        float ckv = cks[kg];
        const int* mrow = mask + (b * NSQ + q0 + qh) * NSK + kg;
#pragma unroll
        for (int q = 0; q < 4; q++) {
            float2 p = unpack2(acc[q]);
            float s = p.x + p.y + cas[qh + q] + ckv;
            if (mrow[q * NSK] == 0) s = -1e9f;
            scT[(qh + q) * SCP + kg] = s;
        }
    }
    __syncthreads();

    // softmax: warp w handles q = 2w, 2w+1; write normalized attn to gmem
    {
        int w = tid >> 5, lane = tid & 31;
#pragma unroll
        for (int qq = 0; qq < 2; qq++) {
            int q = w * 2 + qq;
            float4 v[4];
            float mx = -3.0e38f;
#pragma unroll
            for (int j = 0; j < 4; j++) {
                v[j] = *(float4*)&scT[q * SCP + j * 128 + lane * 4];
                mx = fmaxf(mx, fmaxf(fmaxf(v[j].x, v[j].y), fmaxf(v[j].z, v[j].w)));
            }
#pragma unroll
            for (int o = 16; o; o >>= 1) mx = fmaxf(mx, __shfl_xor_sync(0xffffffffu, mx, o));
            float sum = 0.f;
#pragma unroll
            for (int j = 0; j < 4; j++) {
                v[j].x = __expf(v[j].x - mx); v[j].y = __expf(v[j].y - mx);
                v[j].z = __expf(v[j].z - mx); v[j].w = __expf(v[j].w - mx);
                sum += v[j].x + v[j].y + v[j].z + v[j].w;
            }
#pragma unroll
            for (int o = 16; o; o >>= 1) sum += __shfl_xor_sync(0xffffffffu, sum, o);
            float inv = 1.0f / sum;
            float* arow = attn_out + (b * NSQ + q0 + q) * NSK;
#pragma unroll
            for (int j = 0; j < 4; j++) {
                float4 wv;
                wv.x = v[j].x * inv; wv.y = v[j].y * inv;
                wv.z = v[j].z * inv; wv.w = v[j].w * inv;
                *(float4*)&arow[j * 128 + lane * 4] = wv;
            }
        }
    }
}

// ---------------------------------------------------------------------------
// AV GEMM (R8 structure, 256 thr, BM=64 x BN=128 x BK=16, double-buffered).
// Diet: q-pairs read PRE-PACKED from At (ulonglong2); only 4 V-side packs/kk.
// Warp owns 16 d; thread = 8q(4 pairs) x 4d. grid (4,8,4)=128.
// ---------------------------------------------------------------------------
#define ATP 68
#define BVP 132

__global__ __launch_bounds__(256) void av_kernel(const float* __restrict__ attn,
                                                 const float* __restrict__ Vv,
                                                 float* __restrict__ out) {
    int b  = blockIdx.z;
    int q0 = blockIdx.y * 64;
    int d0 = blockIdx.x * 128;
    int tid = threadIdx.x;
    int w = tid >> 5, lane = tid & 31;
    int qc = lane >> 2, dc = lane & 3;

    __shared__ float At[2][16][ATP];   // attn^T tile [k][q]
    __shared__ float Bs[2][16][BVP];   // V tile [k][d]

    const float* Ab = attn + (b * NSQ + q0) * NSK;
    const float* Vb = Vv + b * NSK * ND + d0;

    int ra = tid >> 2, ca = (tid & 3) * 4;        // attn: q=ra, k=ca..ca+3
    int rb0 = tid >> 5, cb0 = (tid & 31) * 4;     // V: k rows rb0, rb0+8

    float4 a  = *(const float4*)&Ab[ra * NSK + ca];
    float4 v0 = *(const float4*)&Vb[rb0 * ND + cb0];
    float4 v1 = *(const float4*)&Vb[(rb0 + 8) * ND + cb0];
    At[0][ca][ra] = a.x; At[0][ca + 1][ra] = a.y;
    At[0][ca + 2][ra] = a.z; At[0][ca + 3][ra] = a.w;
    *(float4*)&Bs[0][rb0][cb0] = v0;
    *(float4*)&Bs[0][rb0 + 8][cb0] = v1;
    __syncthreads();

    ull acc[4][4] = {};                // [q-pair][d]
    int db = w * 16 + dc * 4;

    for (int t = 0; t < NSK / 16; t++) {
        int cur = t & 1;
        if (t + 1 < NSK / 16) {
            int k0 = (t + 1) * 16;
            a  = *(const float4*)&Ab[ra * NSK + k0 + ca];
            v0 = *(const float4*)&Vb[(k0 + rb0) * ND + cb0];
            v1 = *(const float4*)&Vb[(k0 + rb0 + 8) * ND + cb0];
        }
#pragma unroll
        for (int kk = 0; kk < 16; kk++) {
            ulonglong2 qp01 = *(ulonglong2*)&At[cur][kk][qc * 8];      // pairs 0,1
            ulonglong2 qp23 = *(ulonglong2*)&At[cur][kk][qc * 8 + 4];  // pairs 2,3
            float4 bv = *(float4*)&Bs[cur][kk][db];                    // 4 distinct/warp
            ull vd0 = pack2(bv.x, bv.x), vd1 = pack2(bv.y, bv.y);
            ull vd2 = pack2(bv.z, bv.z), vd3 = pack2(bv.w, bv.w);
            fma2(acc[0][0], qp01.x, vd0); fma2(acc[0][1], qp01.x, vd1);
            fma2(acc[0][2], qp01.x, vd2); fma2(acc[0][3], qp01.x, vd3);
            fma2(acc[1][0], qp01.y, vd0); fma2(acc[1][1], qp01.y, vd1);
            fma2(acc[1][2], qp01.y, vd2); fma2(acc[1][3], qp01.y, vd3);
            fma2(acc[2][0], qp23.x, vd0); fma2(acc[2][1], qp23.x, vd1);
            fma2(acc[2][2], qp23.x, vd2); fma2(acc[2][3], qp23.x, vd3);
            fma2(acc[3][0], qp23.y, vd0); fma2(acc[3][1], qp23.y, vd1);
            fma2(acc[3][2], qp23.y, vd2); fma2(acc[3][3], qp23.y, vd3);
        }
        if (t + 1 < NSK / 16) {
            int nxt = cur ^ 1;
            At[nxt][ca][ra] = a.x; At[nxt][ca + 1][ra] = a.y;
            At[nxt][ca + 2][ra] = a.z; At[nxt][ca + 3][ra] = a.w;
            *(float4*)&Bs[nxt][rb0][cb0] = v0;
            *(float4*)&Bs[nxt][rb0 + 8][cb0] = v1;
        }
        __syncthreads();
    }

    // epilogue: acc[j][d] = (out[q2j][d], out[q2j+1][d])
    float* Ob = out + (b * NSQ + q0 + qc * 8) * ND + d0 + db;
#pragma unroll
    for (int j = 0; j < 4; j++) {
        float2 t0 = unpack2(acc[j][0]), t1 = unpack2(acc[j][1]);
        float2 t2 = unpack2(acc[j][2]), t3 = unpack2(acc[j][3]);
        float4 rlo = make_float4(t0.x, t1.x, t2.x, t3.x);
        float4 rhi = make_float4(t0.y, t1.y, t2.y, t3.y);
        *(float4*)&Ob[(2 * j) * ND]     = rlo;
        *(float4*)&Ob[(2 * j + 1) * ND] = rhi;
    }
}

// ---------------------------------------------------------------------------
#define SMEM_SC ((TQ * NS + NS + NSK + 16 + KT * KMP + TQ * SCP) * 4)

extern "C" void kernel_launch(void* const* d_in, const int* in_sizes, int n_in,
                              void* d_out, int out_size) {
    const float* query = (const float*)d_in[0];
    const float* key   = (const float*)d_in[1];
    const float* value = (const float*)d_in[2];
    const int*   mask  = (const int*)d_in[3];
    const float* Wq = (const float*)d_in[4];
    const float* bq = (const float*)d_in[5];
    const float* Wk = (const float*)d_in[6];
    const float* bk = (const float*)d_in[7];
    const float* W1 = (const float*)d_in[8];
    const float* b1 = (const float*)d_in[9];
    const float* W2 = (const float*)d_in[10];
    const float* b2 = (const float*)d_in[11];

    float* out  = (float*)d_out;
    float* attn = out + NB * NSQ * ND;

    cudaFuncSetAttribute(score_kernel,
                         cudaFuncAttributeMaxDynamicSharedMemorySize, SMEM_SC);

    fold_kernel<<<dim3(65, 2), 128>>>(Wq, Wk, W1, bq, bk, b1, W2);
    proj_kernel<<<dim3(64, 2), 256>>>(query, key, W2);
    score_kernel<<<NB * NSQ / TQ, 128, SMEM_SC>>>(mask, b2, attn);
    av_kernel<<<dim3(4, 8, 4), 256>>>(attn, value, out);
}